// round 14
// baseline (speedup 1.0000x reference)
#include <cuda_runtime.h>
#include <cstdint>

#define TT   512
#define VV   32
#define LSC  176          // scan length each direction (multiple of 4)
#define MID  160          // middle chunk steps (512 - 2*176)
#define RD   4            // scan ring depth
#define NSTG 4            // chunk ring depth
#define NTHR 256
#define F_LOG2E 1.4426950408889634f
#define F_LN2   0.6931471805599453f

typedef unsigned long long ull;

__device__ float g_P[64*VV*VV];
__device__ float g_Ac[64];
__device__ int   g_flag[64];     // zero-init; consumer resets after use (replay-safe)

__device__ __forceinline__ float ex2f_(float x){ float y; asm("ex2.approx.ftz.f32 %0, %1;" : "=f"(y) : "f"(x)); return y; }
__device__ __forceinline__ float lg2f_(float x){ float y; asm("lg2.approx.ftz.f32 %0, %1;" : "=f"(y) : "f"(x)); return y; }
__device__ __forceinline__ ull fma2_(ull a, ull b, ull c){ ull r; asm("fma.rn.f32x2 %0, %1, %2, %3;" : "=l"(r) : "l"(a), "l"(b), "l"(c)); return r; }
__device__ __forceinline__ void unpack2_(ull v, float& lo, float& hi){ asm("mov.b64 {%0, %1}, %2;" : "=f"(lo), "=f"(hi) : "l"(v)); }
__device__ __forceinline__ void cpa16(uint32_t s, const void* g){
  asm volatile("cp.async.cg.shared.global [%0], [%1], 16;" :: "r"(s), "l"(g));
}
#define CPCOMMIT() asm volatile("cp.async.commit_group;")
#define CPWAIT3()  asm volatile("cp.async.wait_group 3;")
#define CPWAIT2()  asm volatile("cp.async.wait_group 2;")

__device__ __forceinline__ void st_release_(int* p, int v){
  asm volatile("st.release.gpu.global.s32 [%0], %1;" :: "l"(p), "r"(v) : "memory");
}
__device__ __forceinline__ int ld_acquire_(const int* p){
  int v; asm volatile("ld.acquire.gpu.global.s32 %0, [%1];" : "=r"(v) : "l"(p) : "memory");
  return v;
}

__device__ __forceinline__ int tgt_is64(const int* t32){
  int is64 = 1;
  #pragma unroll
  for (int k = 1; k < 64; k += 2) if (t32[k] != 0) is64 = 0;
  return is64;
}
__device__ __forceinline__ int ld_tgt(const void* traw, int is64, long long idx){
  return is64 ? (int)((const long long*)traw)[idx] : ((const int*)traw)[idx];
}

__global__ __launch_bounds__(NTHR, 1)
void crf_main(const float* __restrict__ scores,
              const void*  __restrict__ traw,
              const float* __restrict__ w_tx,
              const float* __restrict__ w_init,
              const float* __restrict__ w_final,
              const float* __restrict__ w_dur,
              float* __restrict__ out)
{
  __shared__ __align__(16) char pool[34624];
  const int bid  = blockIdx.x;
  const int tid  = threadIdx.x;
  const int lane = tid & 31;
  const int wid  = tid >> 5;

  if (bid < 64){
    // ================= SCAN CTA: warps 0/1 run R13 scan; warps 2-7 park ==============
    const int b = bid;
    float (*ring)[RD*1024] = (float(*)[RD*1024])(pool);      // 2 x 16KB
    float (*exch)[VV]      = (float(*)[VV])(pool + 32768);   // 2 x 32
    float* numsm           = (float*)(pool + 33024);         // 256
    int*   Ash             = (int*)  (pool + 34048);         // 2
    const float* sb = scores + (size_t)b * TT * 1024;

    if (wid < 2){
      const uint32_t rbase = (uint32_t)__cvta_generic_to_shared(&ring[wid][0]);
      const char*    rptr  = (const char*)&ring[wid][0];

      uint32_t dsto[8];
      #pragma unroll
      for (int i = 0; i < 8; ++i){
        int g = i*32 + lane, row = g >> 3, c4 = g & 7;
        dsto[i] = (uint32_t)(row*128 + ((c4 ^ (row & 7)) * 16));
      }

      float c2[VV], u;
      if (wid == 0){
        #pragma unroll
        for (int i = 0; i < VV; ++i) c2[i] = (w_tx[i*VV + lane] + w_dur[i*VV + lane]) * F_LOG2E;
        u = ex2f_(w_init[lane] * F_LOG2E);
      } else {
        #pragma unroll
        for (int i = 0; i < VV; ++i) c2[i] = (w_tx[lane*VV + i] + w_dur[lane*VV + i]) * F_LOG2E;
        u = ex2f_(w_final[lane] * F_LOG2E);
      }

      int A = 0;

      if (wid == 0){
        // FORWARD
        #pragma unroll
        for (int p = 0; p < RD-1; ++p){
          const char* g = (const char*)(sb + (size_t)p*1024);
          #pragma unroll
          for (int i = 0; i < 8; ++i) cpa16(rbase + (uint32_t)p*4096u + dsto[i], g + i*512 + lane*16);
          CPCOMMIT();
        }
        uint32_t off8[8];
        #pragma unroll
        for (int k = 0; k < 8; ++k) off8[k] = (uint32_t)((((lane>>2) ^ k) * 16) + (lane & 3) * 4);

        for (int tb = 0; tb < LSC; tb += 4){
          #pragma unroll
          for (int q = 0; q < 4; ++q){
            const int t = tb + q;
            { const int tl = t + RD - 1;
              if (tl < LSC){
                const char* g = (const char*)(sb + (size_t)tl*1024);
                const uint32_t d = rbase + (uint32_t)(tl & (RD-1)) * 4096u;
                #pragma unroll
                for (int i = 0; i < 8; ++i) cpa16(d + dsto[i], g + i*512 + lane*16);
              }
              CPCOMMIT();
            }
            CPWAIT3();
            __syncwarp();
            const char* tp = rptr + (t & (RD-1))*4096;
            float a0=0.f, a1=0.f, a2=0.f, a3=0.f;
            #pragma unroll
            for (int i = 0; i < VV; i += 4){
              float s0 = *(const float*)(tp + (i  )*128 + off8[(i  ) & 7]);
              float s1 = *(const float*)(tp + (i+1)*128 + off8[(i+1) & 7]);
              float s2 = *(const float*)(tp + (i+2)*128 + off8[(i+2) & 7]);
              float s3 = *(const float*)(tp + (i+3)*128 + off8[(i+3) & 7]);
              float u0 = __shfl_sync(0xffffffffu, u, i  );
              float u1 = __shfl_sync(0xffffffffu, u, i+1);
              float u2 = __shfl_sync(0xffffffffu, u, i+2);
              float u3 = __shfl_sync(0xffffffffu, u, i+3);
              a0 = fmaf(ex2f_(fmaf(s0, F_LOG2E, c2[i  ])), u0, a0);
              a1 = fmaf(ex2f_(fmaf(s1, F_LOG2E, c2[i+1])), u1, a1);
              a2 = fmaf(ex2f_(fmaf(s2, F_LOG2E, c2[i+2])), u2, a2);
              a3 = fmaf(ex2f_(fmaf(s3, F_LOG2E, c2[i+3])), u3, a3);
            }
            u = (a0 + a1) + (a2 + a3);
          }
          float m = u;
          #pragma unroll
          for (int o = 16; o; o >>= 1) m = fmaxf(m, __shfl_xor_sync(0xffffffffu, m, o));
          int esh = ((__float_as_int(m) >> 23) & 255) - 127;
          esh = esh < -126 ? -126 : (esh > 126 ? 126 : esh);
          u *= __int_as_float((127 - esh) << 23);
          A += esh;
        }
      } else {
        // BACKWARD
        #pragma unroll
        for (int p = 0; p < RD-1; ++p){
          const char* g = (const char*)(sb + (size_t)(TT-1-p)*1024);
          #pragma unroll
          for (int i = 0; i < 8; ++i) cpa16(rbase + (uint32_t)p*4096u + dsto[i], g + i*512 + lane*16);
          CPCOMMIT();
        }
        uint32_t roff[8];
        #pragma unroll
        for (int k = 0; k < 8; ++k) roff[k] = (uint32_t)((k ^ (lane & 7)) * 16);
        const uint32_t lrow = (uint32_t)(lane*128);

        for (int tb = 0; tb < LSC; tb += 4){
          #pragma unroll
          for (int q = 0; q < 4; ++q){
            const int t = tb + q;
            { const int tl = t + RD - 1;
              if (tl < LSC){
                const char* g = (const char*)(sb + (size_t)(TT-1-tl)*1024);
                const uint32_t d = rbase + (uint32_t)(tl & (RD-1)) * 4096u;
                #pragma unroll
                for (int i = 0; i < 8; ++i) cpa16(d + dsto[i], g + i*512 + lane*16);
              }
              CPCOMMIT();
            }
            CPWAIT3();
            __syncwarp();
            const char* tp = rptr + (t & (RD-1))*4096 + lrow;
            float a0=0.f, a1=0.f, a2=0.f, a3=0.f;
            #pragma unroll
            for (int c4 = 0; c4 < 8; ++c4){
              float4 v = *(const float4*)(tp + roff[c4]);
              const int jj = c4*4;
              float u0 = __shfl_sync(0xffffffffu, u, jj  );
              float u1 = __shfl_sync(0xffffffffu, u, jj+1);
              float u2 = __shfl_sync(0xffffffffu, u, jj+2);
              float u3 = __shfl_sync(0xffffffffu, u, jj+3);
              a0 = fmaf(ex2f_(fmaf(v.x, F_LOG2E, c2[jj  ])), u0, a0);
              a1 = fmaf(ex2f_(fmaf(v.y, F_LOG2E, c2[jj+1])), u1, a1);
              a2 = fmaf(ex2f_(fmaf(v.z, F_LOG2E, c2[jj+2])), u2, a2);
              a3 = fmaf(ex2f_(fmaf(v.w, F_LOG2E, c2[jj+3])), u3, a3);
            }
            u = (a0 + a1) + (a2 + a3);
          }
          float m = u;
          #pragma unroll
          for (int o = 16; o; o >>= 1) m = fmaxf(m, __shfl_xor_sync(0xffffffffu, m, o));
          int esh = ((__float_as_int(m) >> 23) & 255) - 127;
          esh = esh < -126 ? -126 : (esh > 126 ? 126 : esh);
          u *= __int_as_float((127 - esh) << 23);
          A += esh;
        }
      }

      exch[wid][lane] = u;
      if (lane == 0) Ash[wid] = A;
    }

    // numerator: 256 threads, steps [tid*2, tid*2+2)
    const int is64 = tgt_is64((const int*)traw);
    const long long tbase = (long long)b * (TT+1);
    float np = 0.f;
    int tga = ld_tgt(traw, is64, tbase + tid*2);
    #pragma unroll
    for (int k = 0; k < 2; ++k){
      int tgb = ld_tgt(traw, is64, tbase + tid*2 + k + 1);
      int ix = tga*VV + tgb;
      np += sb[(size_t)(tid*2 + k)*1024 + ix] + w_tx[ix] + w_dur[ix];
      tga = tgb;
    }
    numsm[tid] = np;
    __syncthreads();

    if (wid == 0){
      float alpha = exch[0][lane];
      float beta  = exch[1][lane];
      float ns = 0.f;
      #pragma unroll
      for (int g8 = 0; g8 < 8; ++g8) ns += numsm[g8*32 + lane];

      if (lane == 0){ while (ld_acquire_(&g_flag[b]) == 0) {} }
      __syncwarp();

      const float* P = &g_P[(size_t)b * 1024];
      float n0=0.f, n1=0.f, n2=0.f, n3=0.f;
      #pragma unroll
      for (int i = 0; i < 32; i += 4){
        float p0 = P[(i  )*VV + lane];
        float p1 = P[(i+1)*VV + lane];
        float p2 = P[(i+2)*VV + lane];
        float p3 = P[(i+3)*VV + lane];
        n0 = fmaf(__shfl_sync(0xffffffffu, alpha, i  ), p0, n0);
        n1 = fmaf(__shfl_sync(0xffffffffu, alpha, i+1), p1, n1);
        n2 = fmaf(__shfl_sync(0xffffffffu, alpha, i+2), p2, n2);
        n3 = fmaf(__shfl_sync(0xffffffffu, alpha, i+3), p3, n3);
      }
      float term = ((n0 + n1) + (n2 + n3)) * beta;
      #pragma unroll
      for (int o = 16; o; o >>= 1){
        term += __shfl_xor_sync(0xffffffffu, term, o);
        ns   += __shfl_xor_sync(0xffffffffu, ns,   o);
      }

      if (lane == 0){
        int t0 = ld_tgt(traw, is64, tbase);
        int tT = ld_tgt(traw, is64, tbase + TT);
        float num = ns + w_init[t0] + w_final[tT];
        out[b] = num - F_LN2 * (lg2f_(term) + (float)(Ash[0] + Ash[1]) + g_Ac[b]);
        g_flag[b] = 0;   // reset for next replay (kernel boundary orders it)
      }
    }

  } else {
    // ================= CHUNK CTA (8 warps): P = prod E_t, t in [LSC, LSC+MID) =========
    // raw tile ring [0,16384), E_cm double buf [16384,24576), P double buf [24576,32768)
    const int b = bid - 64;
    char*  tilec = pool;
    char*  Ecm   = pool + 16384;           // column-major, XOR-swizzled 16B chunks
    float* P_sm  = (float*)(pool + 24576); // row-major [r*32+j], double buffered
    const float* sb = scores + ((size_t)b*TT + LSC) * 1024;
    const uint32_t tbase_s = (uint32_t)__cvta_generic_to_shared(tilec);

    // cp.async: thread g=tid loads 16B chunk g (row=g>>3, c4=g&7) with XOR swizzle
    const int trow = tid >> 3, tc4 = tid & 7;
    const uint32_t mydst = (uint32_t)(trow*128 + ((tc4 ^ (trow & 7)) * 16));

    #pragma unroll
    for (int p = 0; p < NSTG-1; ++p){
      cpa16(tbase_s + (uint32_t)p*4096u + mydst, (const char*)sb + (size_t)p*4096 + tid*16);
      CPCOMMIT();
    }

    // E-build assignment: column c = lane, rows i = 4*wid .. 4*wid+3
    const int ec = lane, ek = wid;
    float c2own[4];
    #pragma unroll
    for (int m = 0; m < 4; ++m){
      int cell = (4*ek + m)*VV + ec;
      c2own[m] = (w_tx[cell] + w_dur[cell]) * F_LOG2E;
    }
    // raw-tile read offsets for my 4 cells: row i, byte col ec*4
    uint32_t rawoff[4];
    #pragma unroll
    for (int m = 0; m < 4; ++m){
      int i = 4*ek + m;
      rawoff[m] = (uint32_t)(i*128 + (((ec>>2) ^ (i & 7)) * 16) + (ec & 3)*4);
    }
    // E_cm write address (chunk ek of column ec)
    char* ewr = Ecm + ec*128 + ((ek ^ (ec & 7)) * 16);
    // E_cm read offsets for column = lane
    uint32_t eroff[8];
    #pragma unroll
    for (int k = 0; k < 8; ++k) eroff[k] = (uint32_t)(lane*128 + ((k ^ (lane & 7)) * 16));

    int A = 0;

    for (int t = 0; t < MID; ++t){
      CPWAIT2();                    // tile t resident (warp-private rows)
      __syncwarp();
      const int slot = t & (NSTG-1);
      const int eb = t & 1;
      {
        const char* tp = tilec + slot*4096;
        float e0 = ex2f_(fmaf(*(const float*)(tp + rawoff[0]), F_LOG2E, c2own[0]));
        float e1 = ex2f_(fmaf(*(const float*)(tp + rawoff[1]), F_LOG2E, c2own[1]));
        float e2 = ex2f_(fmaf(*(const float*)(tp + rawoff[2]), F_LOG2E, c2own[2]));
        float e3 = ex2f_(fmaf(*(const float*)(tp + rawoff[3]), F_LOG2E, c2own[3]));
        if (t == 0){
          // seed P = E_0, row-major linear
          P_sm[(4*ek  )*VV + ec] = e0;
          P_sm[(4*ek+1)*VV + ec] = e1;
          P_sm[(4*ek+2)*VV + ec] = e2;
          P_sm[(4*ek+3)*VV + ec] = e3;
        } else {
          *(float4*)(ewr + eb*4096) = make_float4(e0, e1, e2, e3);
        }
      }
      __syncthreads();   // E (or P seed) visible; previous P_new p00 visible

      { int tl = t + NSTG - 1;
        if (tl < MID)
          cpa16(tbase_s + (uint32_t)(tl & (NSTG-1))*4096u + mydst,
                (const char*)sb + (size_t)tl*4096 + tid*16);
        CPCOMMIT();
      }

      if (t > 0){
        const int pbR = (t-1) & 1, pbW = t & 1;
        const float* Pr = P_sm + pbR*1024;
        float* Pw = P_sm + pbW*1024;

        float p00 = Pr[0];
        int esh = ((__float_as_int(p00) >> 23) & 255) - 127;
        float sc = __int_as_float((127 - esh) << 23);
        A += esh;

        // my E column as f32x2 pairs
        ull Ep[16];
        #pragma unroll
        for (int k = 0; k < 8; ++k){
          ulonglong2 q = *(const ulonglong2*)(Ecm + eb*4096 + eroff[k]);
          Ep[2*k] = q.x; Ep[2*k+1] = q.y;
        }

        // rows r = 4*wid + m (warp-private P rows)
        #pragma unroll
        for (int m = 0; m < 4; ++m){
          const float* Prow = Pr + (4*wid + m)*VV;
          ull acc = 0ull;
          #pragma unroll
          for (int k = 0; k < 8; ++k){
            ulonglong2 pq = *(const ulonglong2*)(Prow + 4*k);   // broadcast
            acc = fma2_(pq.x, Ep[2*k],   acc);
            acc = fma2_(pq.y, Ep[2*k+1], acc);
          }
          float lo, hi; unpack2_(acc, lo, hi);
          Pw[(4*wid + m)*VV + lane] = (lo + hi) * sc;
        }
      }
    }
    __syncthreads();
    const float* Pf = P_sm + ((MID-1) & 1)*1024;
    float* gout = &g_P[(size_t)b * 1024];
    for (int k = tid; k < 1024; k += NTHR) gout[k] = Pf[k];
    if (tid == 0) g_Ac[b] = (float)A;
    __threadfence();
    __syncthreads();
    if (tid == 0) st_release_(&g_flag[b], 1);
  }
}

extern "C" void kernel_launch(void* const* d_in, const int* in_sizes, int n_in,
                              void* d_out, int out_size)
{
  const float* scores  = (const float*)d_in[0];
  const void*  targets = d_in[1];
  const float* w_tx    = (const float*)d_in[2];
  const float* w_init  = (const float*)d_in[3];
  const float* w_final = (const float*)d_in[4];
  const float* w_dur   = (const float*)d_in[5];
  float* out = (float*)d_out;

  crf_main<<<128, NTHR>>>(scores, targets, w_tx, w_init, w_final, w_dur, out);
}

// round 15
// speedup vs baseline: 1.5102x; 1.5102x over previous
#include <cuda_runtime.h>
#include <cstdint>

#define TT   512
#define VV   32
#define LSC  224          // scan steps each direction (multiple of 4)
#define MID  64           // middle chunk steps
#define NB   (LSC/4)      // scan batches
#define NSTG 4            // chunk ring depth
#define NTHR 192
#define F_LOG2E 1.4426950408889634f
#define F_LN2   0.6931471805599453f

// scan smem layout (dynamic)
#define RAWF 0
#define RAWB 32768
#define EF   65536
#define EB   98304
#define EXCH 131072
#define NUMS 131328
#define ASH  132096
#define SMEM_TOTAL 132608

typedef unsigned long long ull;

__device__ float g_P[64*VV*VV];
__device__ float g_Ac[64];
__device__ int   g_flag[64];     // zero-init; consumer resets after use (replay-safe)

__device__ __forceinline__ float ex2f_(float x){ float y; asm("ex2.approx.ftz.f32 %0, %1;" : "=f"(y) : "f"(x)); return y; }
__device__ __forceinline__ float lg2f_(float x){ float y; asm("lg2.approx.ftz.f32 %0, %1;" : "=f"(y) : "f"(x)); return y; }
__device__ __forceinline__ ull fma2_(ull a, ull b, ull c){ ull r; asm("fma.rn.f32x2 %0, %1, %2, %3;" : "=l"(r) : "l"(a), "l"(b), "l"(c)); return r; }
__device__ __forceinline__ ull pack2_(float lo, float hi){ ull r; asm("mov.b64 %0, {%1, %2};" : "=l"(r) : "f"(lo), "f"(hi)); return r; }
__device__ __forceinline__ void unpack2_(ull v, float& lo, float& hi){ asm("mov.b64 {%0, %1}, %2;" : "=f"(lo), "=f"(hi) : "l"(v)); }
__device__ __forceinline__ void cpa16(uint32_t s, const void* g){
  asm volatile("cp.async.cg.shared.global [%0], [%1], 16;" :: "r"(s), "l"(g));
}
#define CPCOMMIT() asm volatile("cp.async.commit_group;")
#define CPWAIT4()  asm volatile("cp.async.wait_group 4;")
#define CPWAIT2()  asm volatile("cp.async.wait_group 2;")
#define CPWAIT0()  asm volatile("cp.async.wait_group 0;")

__device__ __forceinline__ void st_release_(int* p, int v){
  asm volatile("st.release.gpu.global.s32 [%0], %1;" :: "l"(p), "r"(v) : "memory");
}
__device__ __forceinline__ int ld_acquire_(const int* p){
  int v; asm volatile("ld.acquire.gpu.global.s32 %0, [%1];" : "=r"(v) : "l"(p) : "memory");
  return v;
}
__device__ __forceinline__ int tgt_is64(const int* t32){
  int is64 = 1;
  #pragma unroll
  for (int k = 1; k < 64; k += 2) if (t32[k] != 0) is64 = 0;
  return is64;
}
__device__ __forceinline__ int ld_tgt(const void* traw, int is64, long long idx){
  return is64 ? (int)((const long long*)traw)[idx] : ((const int*)traw)[idx];
}

extern __shared__ __align__(16) char pool[];

__global__ __launch_bounds__(NTHR, 1)
void crf_main(const float* __restrict__ scores,
              const void*  __restrict__ traw,
              const float* __restrict__ w_tx,
              const float* __restrict__ w_init,
              const float* __restrict__ w_final,
              const float* __restrict__ w_dur,
              float* __restrict__ out)
{
  const int bid  = blockIdx.x;
  const int tid  = threadIdx.x;
  const int lane = tid & 31;
  const int wid  = tid >> 5;

  if (bid < 64){
    // ========================= SCAN CTA: 2 chains x (1 consumer + 2 producers) ======
    const int b = bid;
    const float* sb = scores + (size_t)b * TT * 1024;
    const int chain = wid & 1;      // 0 = forward, 1 = backward
    const int role  = wid >> 1;     // 0 consumer, 1/2 producer
    char* rawP = pool + (chain ? RAWB : RAWF);
    char* eP   = pool + (chain ? EB   : EF);
    float (*exch)[VV] = (float(*)[VV])(pool + EXCH);
    float* numsm = (float*)(pool + NUMS);
    int*   Ash   = (int*)(pool + ASH);

    if (role == 0){
      // ---------------- CONSUMER: pure recurrence on pre-exp'd tiles ----------------
      float u = ex2f_((chain ? w_final[lane] : w_init[lane]) * F_LOG2E);
      uint32_t roffc[8];
      #pragma unroll
      for (int k = 0; k < 8; ++k) roffc[k] = (uint32_t)(lane*128 + ((k ^ (lane & 7)) * 16));
      int A = 0;

      for (int kb = 0; kb < NB; ++kb){
        asm volatile("bar.sync %0, 96;" :: "r"(1 + chain) : "memory");
        const char* base = eP + (kb & 1)*16384;
        #pragma unroll
        for (int q = 0; q < 4; ++q){
          const char* tp = base + q*4096;
          float a0=0.f, a1=0.f, a2=0.f, a3=0.f;
          #pragma unroll
          for (int k = 0; k < 8; ++k){
            float4 v = *(const float4*)(tp + roffc[k]);
            const int jj = 4*k;
            float u0 = __shfl_sync(0xffffffffu, u, jj  );
            float u1 = __shfl_sync(0xffffffffu, u, jj+1);
            float u2 = __shfl_sync(0xffffffffu, u, jj+2);
            float u3 = __shfl_sync(0xffffffffu, u, jj+3);
            a0 = fmaf(v.x, u0, a0);
            a1 = fmaf(v.y, u1, a1);
            a2 = fmaf(v.z, u2, a2);
            a3 = fmaf(v.w, u3, a3);
          }
          u = (a0 + a1) + (a2 + a3);
        }
        // renorm every 4 steps: warp-max exponent, exact pow2
        float m = u;
        #pragma unroll
        for (int o = 16; o; o >>= 1) m = fmaxf(m, __shfl_xor_sync(0xffffffffu, m, o));
        int esh = ((__float_as_int(m) >> 23) & 255) - 127;
        esh = esh < -126 ? -126 : (esh > 126 ? 126 : esh);
        u *= __int_as_float((127 - esh) << 23);
        A += esh;
      }
      exch[chain][lane] = u;
      if (lane == 0) Ash[chain] = A;

    } else {
      // ---------------- PRODUCER pp: exp 16 of 32 rows/cols per tile ----------------
      const int pp = role - 1;
      const uint32_t rawu = (uint32_t)__cvta_generic_to_shared(rawP);

      uint32_t rdst[4], rsrc[4], ewr[4], poff[16];
      float c2p[16];
      if (chain == 0){
        // fwd: my rows i in [16pp,16pp+16); compute column j=lane of e_cm[j][i]
        #pragma unroll
        for (int q = 0; q < 4; ++q){
          int m = q*32 + lane, row = 16*pp + (m >> 3), c4 = m & 7;
          rdst[q] = (uint32_t)(row*128 + ((c4 ^ (row & 7)) * 16));
          rsrc[q] = (uint32_t)(row*128 + c4*16);
        }
        #pragma unroll
        for (int m = 0; m < 16; ++m){
          int i = 16*pp + m, cell = i*VV + lane;
          c2p[m] = (w_tx[cell] + w_dur[cell]) * F_LOG2E;
          poff[m] = (uint32_t)(i*128 + (((lane>>2) ^ (i & 7)) * 16) + (lane & 3)*4);
        }
        #pragma unroll
        for (int mm = 0; mm < 4; ++mm){
          int c4 = 4*pp + mm;
          ewr[mm] = (uint32_t)(lane*128 + ((c4 ^ (lane & 7)) * 16));
        }
      } else {
        // bwd: my cols j in [16pp,16pp+16); row i=lane of e_rm[i][j]; read offs == write offs
        #pragma unroll
        for (int q = 0; q < 4; ++q){
          int m = q*32 + lane, row = m >> 2, c4 = 4*pp + (m & 3);
          rdst[q] = (uint32_t)(row*128 + ((c4 ^ (row & 7)) * 16));
          rsrc[q] = (uint32_t)(row*128 + c4*16);
        }
        #pragma unroll
        for (int m = 0; m < 16; ++m){
          int cell = lane*VV + 16*pp + m;
          c2p[m] = (w_tx[cell] + w_dur[cell]) * F_LOG2E;
        }
        #pragma unroll
        for (int mm = 0; mm < 4; ++mm){
          int c4 = 4*pp + mm;
          ewr[mm] = (uint32_t)(lane*128 + ((c4 ^ (lane & 7)) * 16));
        }
      }

      // request batches 0,1
      #pragma unroll
      for (int bt = 0; bt < 2; ++bt){
        #pragma unroll
        for (int tt = 0; tt < 4; ++tt){
          int t = bt*4 + tt;
          const char* g = (const char*)sb + (size_t)(chain ? (TT-1-t) : t)*4096;
          uint32_t d = rawu + (uint32_t)((bt & 1)*16384 + tt*4096);
          #pragma unroll
          for (int q = 0; q < 4; ++q) cpa16(d + rdst[q], g + rsrc[q]);
          CPCOMMIT();
        }
      }
      CPWAIT4();
      __syncwarp();

      // produce one batch into e ring
      #define PRODUCE(BT)                                                        \
        {                                                                        \
          const char* rset = rawP + ((BT) & 1)*16384;                            \
          char* eset = eP + ((BT) & 1)*16384;                                    \
          _Pragma("unroll")                                                      \
          for (int tt = 0; tt < 4; ++tt){                                        \
            const char* tp = rset + tt*4096;                                     \
            char* ed = eset + tt*4096;                                           \
            if (chain == 0){                                                     \
              float e[16];                                                       \
              _Pragma("unroll")                                                  \
              for (int m = 0; m < 16; ++m)                                       \
                e[m] = ex2f_(fmaf(*(const float*)(tp + poff[m]), F_LOG2E, c2p[m]));\
              _Pragma("unroll")                                                  \
              for (int mm = 0; mm < 4; ++mm)                                     \
                *(float4*)(ed + ewr[mm]) =                                       \
                  make_float4(e[4*mm], e[4*mm+1], e[4*mm+2], e[4*mm+3]);         \
            } else {                                                             \
              _Pragma("unroll")                                                  \
              for (int mm = 0; mm < 4; ++mm){                                    \
                float4 v = *(const float4*)(tp + ewr[mm]);                       \
                float4 r;                                                        \
                r.x = ex2f_(fmaf(v.x, F_LOG2E, c2p[4*mm  ]));                    \
                r.y = ex2f_(fmaf(v.y, F_LOG2E, c2p[4*mm+1]));                    \
                r.z = ex2f_(fmaf(v.z, F_LOG2E, c2p[4*mm+2]));                    \
                r.w = ex2f_(fmaf(v.w, F_LOG2E, c2p[4*mm+3]));                    \
                *(float4*)(ed + ewr[mm]) = r;                                    \
              }                                                                  \
            }                                                                    \
          }                                                                      \
        }

      PRODUCE(0)

      for (int kb = 0; kb < NB; ++kb){
        asm volatile("bar.sync %0, 96;" :: "r"(1 + chain) : "memory");
        if (kb + 1 < NB){
          if (kb + 2 < NB){
            const int bt = kb + 2;
            #pragma unroll
            for (int tt = 0; tt < 4; ++tt){
              int t = bt*4 + tt;
              const char* g = (const char*)sb + (size_t)(chain ? (TT-1-t) : t)*4096;
              uint32_t d = rawu + (uint32_t)((bt & 1)*16384 + tt*4096);
              #pragma unroll
              for (int q = 0; q < 4; ++q) cpa16(d + rdst[q], g + rsrc[q]);
              CPCOMMIT();
            }
            CPWAIT4();
          } else {
            CPWAIT0();
          }
          __syncwarp();
          PRODUCE(kb + 1)
        }
      }
      #undef PRODUCE
    }

    // ---------------- numerator: threads 0..127, steps [tid*4, tid*4+4) ----------
    const int is64 = tgt_is64((const int*)traw);
    const long long tbase = (long long)b * (TT+1);
    if (tid < 128){
      float np = 0.f;
      int tga = ld_tgt(traw, is64, tbase + tid*4);
      #pragma unroll
      for (int k = 0; k < 4; ++k){
        int tgb = ld_tgt(traw, is64, tbase + tid*4 + k + 1);
        int ix = tga*VV + tgb;
        np += sb[(size_t)(tid*4 + k)*1024 + ix] + w_tx[ix] + w_dur[ix];
        tga = tgb;
      }
      numsm[tid] = np;
    }
    __syncthreads();

    if (wid == 0){
      float alpha = exch[0][lane];
      float beta  = exch[1][lane];
      float ns = numsm[lane] + numsm[32+lane] + numsm[64+lane] + numsm[96+lane];

      if (lane == 0){ while (ld_acquire_(&g_flag[b]) == 0) {} }
      __syncwarp();

      const float* P = &g_P[(size_t)b * 1024];
      float n0=0.f, n1=0.f, n2=0.f, n3=0.f;
      #pragma unroll
      for (int i = 0; i < 32; i += 4){
        float p0 = P[(i  )*VV + lane];
        float p1 = P[(i+1)*VV + lane];
        float p2 = P[(i+2)*VV + lane];
        float p3 = P[(i+3)*VV + lane];
        n0 = fmaf(__shfl_sync(0xffffffffu, alpha, i  ), p0, n0);
        n1 = fmaf(__shfl_sync(0xffffffffu, alpha, i+1), p1, n1);
        n2 = fmaf(__shfl_sync(0xffffffffu, alpha, i+2), p2, n2);
        n3 = fmaf(__shfl_sync(0xffffffffu, alpha, i+3), p3, n3);
      }
      float term = ((n0 + n1) + (n2 + n3)) * beta;
      #pragma unroll
      for (int o = 16; o; o >>= 1){
        term += __shfl_xor_sync(0xffffffffu, term, o);
        ns   += __shfl_xor_sync(0xffffffffu, ns,   o);
      }
      if (lane == 0){
        int t0 = ld_tgt(traw, is64, tbase);
        int tT = ld_tgt(traw, is64, tbase + TT);
        float num = ns + w_init[t0] + w_final[tT];
        out[b] = num - F_LN2 * (lg2f_(term) + (float)(Ash[0] + Ash[1]) + g_Ac[b]);
        g_flag[b] = 0;
      }
    }

  } else {
    // ================= CHUNK CTA (R13 code; warps 0-3 work, 4-5 ride barriers) ======
    const int b = bid - 64;
    float* tile = (float*)(pool);             // NSTG*4KB
    float* E_sm = (float*)(pool + 16384);     // 2*4KB
    float* P_sm = (float*)(pool + 24576);     // 2*4KB
    const float* sb = scores + ((size_t)b*TT + LSC) * 1024;
    const int j  = lane;
    const int r0 = wid * 8;
    const bool act = (tid < 128);

    float c2own[8];
    if (act){
      #pragma unroll
      for (int p = 0; p < NSTG-1; ++p){
        const uint32_t d = (uint32_t)__cvta_generic_to_shared(&tile[p*1024 + tid*8]);
        cpa16(d,      sb + p*1024 + tid*8);
        cpa16(d + 16, sb + p*1024 + tid*8 + 4);
        CPCOMMIT();
      }
      #pragma unroll
      for (int k = 0; k < 8; ++k)
        c2own[k] = (w_tx[tid*8+k] + w_dur[tid*8+k]) * F_LOG2E;
    }
    __syncthreads();
    int A = 0;

    for (int t = 0; t < MID; ++t){
      const int slot = t & (NSTG-1);
      if (act){
        CPWAIT2();
        const float* tp = &tile[slot*1024 + tid*8];
        float e0 = ex2f_(fmaf(tp[0], F_LOG2E, c2own[0]));
        float e1 = ex2f_(fmaf(tp[1], F_LOG2E, c2own[1]));
        float e2 = ex2f_(fmaf(tp[2], F_LOG2E, c2own[2]));
        float e3 = ex2f_(fmaf(tp[3], F_LOG2E, c2own[3]));
        float e4 = ex2f_(fmaf(tp[4], F_LOG2E, c2own[4]));
        float e5 = ex2f_(fmaf(tp[5], F_LOG2E, c2own[5]));
        float e6 = ex2f_(fmaf(tp[6], F_LOG2E, c2own[6]));
        float e7 = ex2f_(fmaf(tp[7], F_LOG2E, c2own[7]));
        float* dst = (t == 0) ? &P_sm[0*1024 + tid*8] : &E_sm[(t&1)*1024 + tid*8];
        *(float4*)dst       = make_float4(e0, e1, e2, e3);
        *(float4*)(dst + 4) = make_float4(e4, e5, e6, e7);
      }
      __syncthreads();

      if (act){
        int tl = t + NSTG - 1;
        if (tl < MID){
          const uint32_t d = (uint32_t)__cvta_generic_to_shared(&tile[(tl & (NSTG-1))*1024 + tid*8]);
          cpa16(d,      sb + (size_t)tl*1024 + tid*8);
          cpa16(d + 16, sb + (size_t)tl*1024 + tid*8 + 4);
        }
        CPCOMMIT();

        if (t > 0){
          const int pbR = (t-1) & 1, pbW = t & 1, eb = t & 1;
          float p00 = P_sm[pbR*1024];
          int esh = ((__float_as_int(p00) >> 23) & 255) - 127;
          float sc = __int_as_float((127 - esh) << 23);
          A += esh;

          ull E2[16];
          #pragma unroll
          for (int i2 = 0; i2 < 16; ++i2)
            E2[i2] = pack2_(E_sm[eb*1024 + (2*i2)*VV + j], E_sm[eb*1024 + (2*i2+1)*VV + j]);

          ull acc[8];
          #pragma unroll
          for (int r = 0; r < 8; ++r) acc[r] = 0ull;
          #pragma unroll
          for (int i4 = 0; i4 < 8; ++i4){
            #pragma unroll
            for (int r = 0; r < 8; ++r){
              ulonglong2 qq = *(const ulonglong2*)&P_sm[pbR*1024 + (r0+r)*VV + 4*i4];
              acc[r] = fma2_(qq.x, E2[2*i4],   acc[r]);
              acc[r] = fma2_(qq.y, E2[2*i4+1], acc[r]);
            }
          }
          #pragma unroll
          for (int r = 0; r < 8; ++r){
            float lo, hi; unpack2_(acc[r], lo, hi);
            P_sm[pbW*1024 + (r0+r)*VV + j] = (lo + hi) * sc;
          }
        }
      }
    }
    __syncthreads();
    const float* Pf = P_sm + ((MID-1) & 1)*1024;
    float* gout = &g_P[(size_t)b * 1024];
    for (int k = tid; k < 1024; k += NTHR) gout[k] = Pf[k];
    if (tid == 0) g_Ac[b] = (float)A;
    __threadfence();
    __syncthreads();
    if (tid == 0) st_release_(&g_flag[b], 1);
  }
}

extern "C" void kernel_launch(void* const* d_in, const int* in_sizes, int n_in,
                              void* d_out, int out_size)
{
  const float* scores  = (const float*)d_in[0];
  const void*  targets = d_in[1];
  const float* w_tx    = (const float*)d_in[2];
  const float* w_init  = (const float*)d_in[3];
  const float* w_final = (const float*)d_in[4];
  const float* w_dur   = (const float*)d_in[5];
  float* out = (float*)d_out;

  cudaFuncSetAttribute(crf_main, cudaFuncAttributeMaxDynamicSharedMemorySize, SMEM_TOTAL);
  crf_main<<<128, NTHR, SMEM_TOTAL>>>(scores, targets, w_tx, w_init, w_final, w_dur, out);
}